// round 7
// baseline (speedup 1.0000x reference)
#include <cuda_runtime.h>
#include <cstdint>

// Problem constants (D=20, RANK=2 -> o=19 per axis, m=32)
#define O      19
#define DM     20
#define MM     32
#define ROWP   36                    // padded row -> conflict-free LDS.128
#define CT_STRIDE (MM*ROWP)          // 1152 floats per cos-table slab
#define NT     640                   // 20 warps: (c-pair 0..9) x (d-group 0..1)
#define NITEMS (O*O*2)               // (a,b) x d-half

typedef unsigned long long ull;

// ---- packed f32x2 helpers ----
__device__ __forceinline__ ull f2mul(ull a, ull b) {
    ull r; asm("mul.rn.f32x2 %0, %1, %2;" : "=l"(r) : "l"(a), "l"(b)); return r;
}
__device__ __forceinline__ ull f2fma(ull a, ull b, ull c) {
    ull r; asm("fma.rn.f32x2 %0, %1, %2, %3;" : "=l"(r) : "l"(a), "l"(b), "l"(c)); return r;
}
__device__ __forceinline__ float f2sum(ull v) {
    return __uint_as_float((unsigned)v) + __uint_as_float((unsigned)(v >> 32));
}

// Shared memory layout (floats):
//   Ct  [19][32][36]    @ 0      (21888)  cos table (padded rows)
//   R   [2][20][20][32] @ 21888  (25600)  double-buffered (a,b)-pair sums
//   Msc [32][36]        @ 47488  (1152)   M_w / 16
//   X   [20][2][5][32]  @ 48640  (6400)   per-warp private x slots
//   WS  [20][2][32]     @ 55040  (1280)   per-warp ws staging
#define CT_OFF   0
#define R_OFF    21888
#define RBUF     12800
#define MS_OFF   47488
#define X_OFF    48640
#define WS_OFF   55040
#define SMEM_FLOATS 56320
#define SMEM_BYTES (SMEM_FLOATS * 4)    // 225280 B, 1 CTA/SM

// ---- batched MLP-10 R load: R[buf] = 2x2 (a,b) pair-sum ----
__device__ __forceinline__ void load_R(const float* __restrict__ H,
                                       float* __restrict__ Rb,
                                       int A, int B, int tid)
{
    const int strideB = DM * DM * MM;        // 12800 floats
    const int strideA = DM * strideB;
    const float4* H00 = (const float4*)(H + (long)A * strideA + (long)B * strideB);
    const float4* H01 = H00 + strideB / 4;
    const float4* H10 = H00 + strideA / 4;
    const float4* H11 = H10 + strideB / 4;
    float4* R4 = (float4*)Rb;

    float4 pa[5], pb[5], acc[5];
    #pragma unroll
    for (int k = 0; k < 5; k++) { pa[k] = H00[tid + k * NT]; pb[k] = H01[tid + k * NT]; }
    #pragma unroll
    for (int k = 0; k < 5; k++)
        acc[k] = make_float4(pa[k].x + pb[k].x, pa[k].y + pb[k].y,
                             pa[k].z + pb[k].z, pa[k].w + pb[k].w);
    #pragma unroll
    for (int k = 0; k < 5; k++) { pa[k] = H10[tid + k * NT]; pb[k] = H11[tid + k * NT]; }
    #pragma unroll
    for (int k = 0; k < 5; k++)
        R4[tid + k * NT] = make_float4(acc[k].x + pa[k].x + pb[k].x,
                                       acc[k].y + pa[k].y + pb[k].y,
                                       acc[k].z + pa[k].z + pb[k].z,
                                       acc[k].w + pa[k].w + pb[k].w);
}

__global__ void __launch_bounds__(NT, 1)
pm4_kernel(const float* __restrict__ H,   // [20,20,20,20,32]
           const float* __restrict__ Mw,  // [32,32]
           const float* __restrict__ P,   // [32,32]
           float* __restrict__ out)       // [19^4, 32]
{
    extern __shared__ float s[];
    float* Ct  = s + CT_OFF;
    float* Msc = s + MS_OFF;

    const int tid  = threadIdx.x;
    const int lane = tid & 31;
    const int w    = tid >> 5;
    const int cp   = w >> 1;          // 0..9
    const int dg   = w & 1;           // 0..1
    const int c0   = 2 * cp;
    const int nc   = (cp == 9) ? 1 : 2;
    const int c1   = (nc == 2) ? c0 + 1 : c0;
    const int g    = gridDim.x;

    float* Xw0 = s + X_OFF + w * 320;         // 5 slots x 32
    float* Xw1 = Xw0 + 160;
    float* ws0 = s + WS_OFF + w * 64;
    float* ws1 = ws0 + 32;

    const float TWO_PI = 6.28318530717958647692f;

    // ---- once per CTA: cos table + prescaled M ----
    for (int e = tid; e < O * MM * MM; e += NT) {
        int n = e >> 10;
        int r = e & 1023;
        int i = r >> 5;
        int j = r & 31;
        float per = (float)(i * MM + j + 2);
        Ct[n * CT_STRIDE + i * ROWP + j] = cosf(TWO_PI * (float)n / per);
    }
    for (int e = tid; e < MM * MM; e += NT) {
        Msc[(e >> 5) * ROWP + (e & 31)] = Mw[e] * 0.0625f;
    }

    // ---- prologue: R for first item into buffer 0 ----
    if (blockIdx.x < NITEMS) {
        int ab0 = blockIdx.x >> 1;
        load_R(H, s + R_OFF, ab0 / O, ab0 % O, tid);
    }
    __syncthreads();

    int buf = 0;
    for (int item = blockIdx.x; item < NITEMS; item += g, buf ^= 1) {
        const int ab = item >> 1;
        const int dh = item & 1;
        const int A = ab / O;
        const int B = ab % O;
        const int dstart = dh ? 10 : 0;
        const int dnum   = dh ? 9 : 10;
        const float* Rb = s + R_OFF + buf * RBUF;

        const int cnt = (dnum - dg + 1) >> 1;   // this warp's window-pair count (<=5)

        // ---- Phase P (per-warp private): ws + matvec -> X slots ----
        {
            ull Mreg[16];
            #pragma unroll
            for (int l4 = 0; l4 < 8; l4++) {
                ulonglong2 m = *reinterpret_cast<const ulonglong2*>(&Msc[lane * ROWP + 4 * l4]);
                Mreg[2 * l4] = m.x; Mreg[2 * l4 + 1] = m.y;
            }
            #pragma unroll 1
            for (int t = 0; t < cnt; t++) {
                const int d = dstart + dg + 2 * t;
                const float* r0 = &Rb[(c0 * DM + d) * MM + lane];
                float rA = r0[0]           + r0[MM];
                float rB = r0[DM * MM]     + r0[DM * MM + MM];
                ws0[lane] = rA + rB;
                if (nc == 2) {
                    float rC = r0[2 * DM * MM] + r0[2 * DM * MM + MM];
                    ws1[lane] = rB + rC;
                }
                __syncwarp();
                ull a0 = 0, a0b = 0, a1 = 0, a1b = 0;
                #pragma unroll
                for (int l4 = 0; l4 < 8; l4++) {
                    ulonglong2 w0 = *reinterpret_cast<const ulonglong2*>(&ws0[4 * l4]);
                    a0  = f2fma(Mreg[2 * l4],     w0.x, a0);
                    a0b = f2fma(Mreg[2 * l4 + 1], w0.y, a0b);
                    if (nc == 2) {
                        ulonglong2 w1 = *reinterpret_cast<const ulonglong2*>(&ws1[4 * l4]);
                        a1  = f2fma(Mreg[2 * l4],     w1.x, a1);
                        a1b = f2fma(Mreg[2 * l4 + 1], w1.y, a1b);
                    }
                }
                Xw0[t * 32 + lane] = f2sum(a0) + f2sum(a0b);
                if (nc == 2) Xw1[t * 32 + lane] = f2sum(a1) + f2sum(a1b);
                __syncwarp();
            }
        }

        // ---- per-warp G = P * Ct[A] * Ct[B] * Ct[c] (P from global, L1-hot) ----
        ull G0[16], G1[16];
        {
            const ulonglong2* Pr  = (const ulonglong2*)(P + lane * MM);
            const float* ca = &Ct[A  * CT_STRIDE + lane * ROWP];
            const float* cb = &Ct[B  * CT_STRIDE + lane * ROWP];
            const float* cc = &Ct[c0 * CT_STRIDE + lane * ROWP];
            const float* cd = &Ct[c1 * CT_STRIDE + lane * ROWP];
            #pragma unroll
            for (int l4 = 0; l4 < 8; l4++) {
                ulonglong2 pv = Pr[l4];
                ulonglong2 av = *reinterpret_cast<const ulonglong2*>(ca + 4 * l4);
                ulonglong2 bv = *reinterpret_cast<const ulonglong2*>(cb + 4 * l4);
                ull gx = f2mul(f2mul(pv.x, av.x), bv.x);
                ull gy = f2mul(f2mul(pv.y, av.y), bv.y);
                ulonglong2 cv = *reinterpret_cast<const ulonglong2*>(cc + 4 * l4);
                ulonglong2 dv = *reinterpret_cast<const ulonglong2*>(cd + 4 * l4);
                G0[2 * l4]     = f2mul(gx, cv.x);
                G0[2 * l4 + 1] = f2mul(gy, cv.y);
                G1[2 * l4]     = f2mul(gx, dv.x);
                G1[2 * l4 + 1] = f2mul(gy, dv.y);
            }
        }

        // ---- Phase C: contraction, same warp, no CTA sync since P ----
        {
            const int outBase = ab * (O * O) * MM;
            #pragma unroll 1
            for (int t = 0; t < cnt; t++) {
                const int d = dstart + dg + 2 * t;
                const float* cdrow = &Ct[d * CT_STRIDE + lane * ROWP];
                const float* xv0p  = &Xw0[t * 32];
                const float* xv1p  = &Xw1[t * 32];
                ull A0 = 0, A0b = 0, A1 = 0, A1b = 0;
                #pragma unroll
                for (int l4 = 0; l4 < 8; l4++) {
                    ulonglong2 cd  = *reinterpret_cast<const ulonglong2*>(cdrow + 4 * l4);
                    ulonglong2 xv0 = *reinterpret_cast<const ulonglong2*>(xv0p + 4 * l4);
                    ulonglong2 xv1 = *reinterpret_cast<const ulonglong2*>(xv1p + 4 * l4);
                    A0  = f2fma(f2mul(cd.x, G0[2 * l4]),     xv0.x, A0);
                    A0b = f2fma(f2mul(cd.y, G0[2 * l4 + 1]), xv0.y, A0b);
                    A1  = f2fma(f2mul(cd.x, G1[2 * l4]),     xv1.x, A1);
                    A1b = f2fma(f2mul(cd.y, G1[2 * l4 + 1]), xv1.y, A1b);
                }
                out[outBase + (c0 * O + d) * MM + lane] = f2sum(A0) + f2sum(A0b);
                if (nc == 2)
                    out[outBase + (c1 * O + d) * MM + lane] = f2sum(A1) + f2sum(A1b);
            }
        }

        // ---- tail: load next item's R into the other buffer ----
        if (item + g < NITEMS) {
            const int ab2 = (item + g) >> 1;
            load_R(H, s + R_OFF + (buf ^ 1) * RBUF, ab2 / O, ab2 % O, tid);
        }
        __syncthreads();   // the single per-item barrier
    }
}

extern "C" void kernel_launch(void* const* d_in, const int* in_sizes, int n_in,
                              void* d_out, int out_size)
{
    const float* H  = (const float*)d_in[0];
    const float* Mw = (const float*)d_in[1];
    const float* P  = (const float*)d_in[2];
    float* out = (float*)d_out;

    cudaFuncSetAttribute(pm4_kernel, cudaFuncAttributeMaxDynamicSharedMemorySize, SMEM_BYTES);

    int dev = 0, nsm = 148;
    cudaGetDevice(&dev);
    cudaDeviceGetAttribute(&nsm, cudaDevAttrMultiProcessorCount, dev);
    if (nsm <= 0) nsm = 148;
    int grid = nsm > NITEMS ? NITEMS : nsm;

    pm4_kernel<<<grid, NT, SMEM_BYTES>>>(H, Mw, P, out);
}

// round 8
// speedup vs baseline: 1.3576x; 1.3576x over previous
#include <cuda_runtime.h>
#include <cstdint>

// Problem constants (D=20, RANK=2 -> o=19 per axis, m=32)
#define O      19
#define DM     20
#define MM     32
#define ROWP   36                    // Ct padded row -> conflict-free LDS.128
#define CT_STRIDE 1152               // 32*36
#define NT     1024                  // 32 warps
#define NWARP  32
#define NITEMS (O*O*2)               // (a,b) x d-half = 722

typedef unsigned long long ull;

// ---- packed f32x2 helpers ----
__device__ __forceinline__ ull f2mul(ull a, ull b) {
    ull r; asm("mul.rn.f32x2 %0, %1, %2;" : "=l"(r) : "l"(a), "l"(b)); return r;
}
__device__ __forceinline__ ull f2fma(ull a, ull b, ull c) {
    ull r; asm("fma.rn.f32x2 %0, %1, %2, %3;" : "=l"(r) : "l"(a), "l"(b), "l"(c)); return r;
}
__device__ __forceinline__ float f2sum(ull v) {
    return __uint_as_float((unsigned)v) + __uint_as_float((unsigned)(v >> 32));
}

// Shared memory layout (floats):
//   Ct  [19][32][36] @ 0      (21888)  cos table, padded rows
//   Gc  [19][32][32] @ 21888  (19456)  P*Ct[A]*Ct[B]*Ct[c], XOR chunk swizzle
//   R'  [20][11][32] @ 41344  (7040)   (a,b)-pair sums / 16, d-slice rows
//   X   [19][10][32] @ 48384  (6080)   x[c,dd,j]
//   WS  [32][32]     @ 54464  (1024)   per-warp staging
#define CT_OFF   0
#define GC_OFF   21888
#define R_OFF    41344
#define X_OFF    48384
#define WS_OFF   54464
#define SMEM_FLOATS 55488
#define SMEM_BYTES (SMEM_FLOATS * 4)   // 221952 B < 227KB opt-in

__global__ void __launch_bounds__(NT, 1)
pm4_kernel(const float* __restrict__ H,   // [20,20,20,20,32]
           const float* __restrict__ Mw,  // [32,32]
           const float* __restrict__ P,   // [32,32]
           float* __restrict__ out)       // [19^4, 32]
{
    extern __shared__ float s[];
    float* Ct = s + CT_OFF;
    float* Gc = s + GC_OFF;
    float* R  = s + R_OFF;
    float* X  = s + X_OFF;
    float* WS = s + WS_OFF;

    const int tid  = threadIdx.x;
    const int lane = tid & 31;
    const int w    = tid >> 5;
    const int m7   = lane & 7;
    const int g    = gridDim.x;

    // per-thread Gc-build role: tid == i0*32 + j0 (exactly 1024 elements)
    const int i0 = tid >> 5;
    const int j0 = tid & 31;
    const int ctij  = i0 * ROWP + j0;                          // Ct row offset
    const int gcij  = i0 * 32 + (((j0 >> 2) ^ (i0 & 7)) << 2) + (j0 & 3);  // swizzled
    const float pv  = P[tid];

    const float TWO_PI = 6.28318530717958647692f;

    // ---- once per CTA: cos table ----
    for (int e = tid; e < O * MM * MM; e += NT) {
        int n = e >> 10;
        int r = e & 1023;
        int i = r >> 5;
        int j = r & 31;
        float per = (float)(i * MM + j + 2);
        Ct[n * CT_STRIDE + i * ROWP + j] = cosf(TWO_PI * (float)n / per);
    }
    __syncthreads();

    float* wsp = WS + w * 32;

    for (int item = blockIdx.x; item < NITEMS; item += g) {
        const int ab = item >> 1;
        const int dh = item & 1;
        const int A  = ab / O;
        const int B  = ab % O;
        const int dstart = dh ? 10 : 0;
        const int dnum   = dh ? 9 : 10;
        const int rows   = dnum + 1;          // R' d-rows needed (10 or 11)

        __syncthreads();   // previous item fully consumed

        // ---- issue R' global loads early (waves overlap Gc build) ----
        const int strideB = DM * DM * MM;      // 12800 floats
        const int strideA = DM * strideB;
        const float4* H00 = (const float4*)(H + (long)A * strideA + (long)B * strideB);
        const float4* H01 = H00 + strideB / 4;
        const float4* H10 = H00 + strideA / 4;
        const float4* H11 = H10 + strideB / 4;
        const int total4 = DM * rows * 8;      // 1600 or 1760 float4
        int gi[2], si[2];
        bool val[2];
        float4 pa[2], pb[2];
        #pragma unroll
        for (int k = 0; k < 2; k++) {
            int e = tid + k * NT;
            val[k] = (e < total4);
            int c  = e / (rows * 8);
            int rm = e - c * rows * 8;
            int dr = rm >> 3;
            int f  = rm & 7;
            gi[k] = (c * DM + dstart + dr) * 8 + f;
            si[k] = (c * 11 + dr) * 8 + f;
            if (val[k]) { pa[k] = H00[gi[k]]; pb[k] = H01[gi[k]]; }
        }

        // ---- Gc build (overlaps the in-flight LDGs) ----
        {
            const float ga = pv * Ct[A * CT_STRIDE + ctij] * Ct[B * CT_STRIDE + ctij];
            #pragma unroll 1
            for (int c = 0; c < O; c++)
                Gc[c * 1024 + gcij] = ga * Ct[c * CT_STRIDE + ctij];
        }

        // ---- finish R' (scale by 1/16) ----
        float4 acc[2];
        #pragma unroll
        for (int k = 0; k < 2; k++) if (val[k])
            acc[k] = make_float4(pa[k].x + pb[k].x, pa[k].y + pb[k].y,
                                 pa[k].z + pb[k].z, pa[k].w + pb[k].w);
        #pragma unroll
        for (int k = 0; k < 2; k++) if (val[k]) { pa[k] = H10[gi[k]]; pb[k] = H11[gi[k]]; }
        float4* R4 = (float4*)R;
        #pragma unroll
        for (int k = 0; k < 2; k++) if (val[k])
            R4[si[k]] = make_float4((acc[k].x + pa[k].x + pb[k].x) * 0.0625f,
                                    (acc[k].y + pa[k].y + pb[k].y) * 0.0625f,
                                    (acc[k].z + pa[k].z + pb[k].z) * 0.0625f,
                                    (acc[k].w + pa[k].w + pb[k].w) * 0.0625f);
        __syncthreads();   // R', Gc ready

        // ---- Phase P: window sums + matvec -> X (lane = j) ----
        {
            ull Mreg[16];
            {
                const ulonglong2* mr = (const ulonglong2*)(Mw + lane * MM);
                #pragma unroll
                for (int k = 0; k < 8; k++) {
                    ulonglong2 m = mr[k];
                    Mreg[2 * k] = m.x; Mreg[2 * k + 1] = m.y;
                }
            }
            const int nwin = O * dnum;
            #pragma unroll 1
            for (int p = w; p < nwin; p += NWARP) {
                const int c  = p / dnum;
                const int dd = p - c * dnum;
                const float* r0 = &R[(c * 11 + dd) * 32 + lane];
                float v = (r0[0] + r0[32]) + (r0[11 * 32] + r0[12 * 32]);
                wsp[lane] = v;
                __syncwarp();
                ull a0 = 0, a1 = 0;
                #pragma unroll
                for (int l4 = 0; l4 < 8; l4++) {
                    ulonglong2 wv = *reinterpret_cast<const ulonglong2*>(&wsp[4 * l4]);
                    a0 = f2fma(Mreg[2 * l4],     wv.x, a0);
                    a1 = f2fma(Mreg[2 * l4 + 1], wv.y, a1);
                }
                X[(c * 10 + dd) * 32 + lane] = f2sum(a0) + f2sum(a1);
                __syncwarp();
            }
        }
        __syncthreads();   // X ready

        // ---- Phase C: unit = (c, d-pair); 95 units / 32 warps; lane = i ----
        {
            const int outBase = ab * (O * O) * MM;
            #pragma unroll 1
            for (int u = w; u < O * 5; u += NWARP) {
                const int c   = u / 5;
                const int dp  = u - c * 5;
                const int dd0 = 2 * dp;
                const int has1 = (dd0 + 1 < dnum);
                const int d0  = dstart + dd0;
                const int d1  = has1 ? d0 + 1 : d0;   // safe read
                const float* gp  = &Gc[c * 1024 + lane * 32];
                const float* cr0 = &Ct[d0 * CT_STRIDE + lane * ROWP];
                const float* cr1 = &Ct[d1 * CT_STRIDE + lane * ROWP];
                const float* x0p = &X[(c * 10 + dd0) * 32];
                const float* x1p = x0p + 32;
                ull A0 = 0, A0b = 0, A1 = 0, A1b = 0;
                #pragma unroll
                for (int l = 0; l < 8; l++) {
                    ulonglong2 gv  = *reinterpret_cast<const ulonglong2*>(gp + ((l ^ m7) << 2));
                    ulonglong2 cd0 = *reinterpret_cast<const ulonglong2*>(cr0 + 4 * l);
                    ulonglong2 xv0 = *reinterpret_cast<const ulonglong2*>(x0p + 4 * l);
                    A0  = f2fma(f2mul(cd0.x, gv.x), xv0.x, A0);
                    A0b = f2fma(f2mul(cd0.y, gv.y), xv0.y, A0b);
                    ulonglong2 cd1 = *reinterpret_cast<const ulonglong2*>(cr1 + 4 * l);
                    ulonglong2 xv1 = *reinterpret_cast<const ulonglong2*>(x1p + 4 * l);
                    A1  = f2fma(f2mul(cd1.x, gv.x), xv1.x, A1);
                    A1b = f2fma(f2mul(cd1.y, gv.y), xv1.y, A1b);
                }
                out[outBase + (c * O + d0) * MM + lane] = f2sum(A0) + f2sum(A0b);
                if (has1)
                    out[outBase + (c * O + d0 + 1) * MM + lane] = f2sum(A1) + f2sum(A1b);
            }
        }
    }
}

extern "C" void kernel_launch(void* const* d_in, const int* in_sizes, int n_in,
                              void* d_out, int out_size)
{
    const float* H  = (const float*)d_in[0];
    const float* Mw = (const float*)d_in[1];
    const float* P  = (const float*)d_in[2];
    float* out = (float*)d_out;

    cudaFuncSetAttribute(pm4_kernel, cudaFuncAttributeMaxDynamicSharedMemorySize, SMEM_BYTES);

    int dev = 0, nsm = 148;
    cudaGetDevice(&dev);
    cudaDeviceGetAttribute(&nsm, cudaDevAttrMultiProcessorCount, dev);
    if (nsm <= 0) nsm = 148;
    int grid = nsm > NITEMS ? NITEMS : nsm;

    pm4_kernel<<<grid, NT, SMEM_BYTES>>>(H, Mw, P, out);
}

// round 9
// speedup vs baseline: 1.7637x; 1.2991x over previous
#include <cuda_runtime.h>
#include <cstdint>

// Problem constants (D=20, RANK=2 -> o=19 per axis, m=32)
#define O      19
#define DM     20
#define MM     32
#define ROWP   36                    // padded row (floats) -> conflict-free LDS.128
#define CT_STRIDE (MM*ROWP)          // 1152 floats per cos-table slab
#define NT     640                   // 20 warps: (c-pair 0..9) x (d-group 0..1)
#define NWARP  20
#define NITEMS (O*O*2)               // (a,b) x d-half

typedef unsigned long long ull;

// ---- packed f32x2 helpers ----
__device__ __forceinline__ ull f2mul(ull a, ull b) {
    ull r; asm("mul.rn.f32x2 %0, %1, %2;" : "=l"(r) : "l"(a), "l"(b)); return r;
}
__device__ __forceinline__ ull f2fma(ull a, ull b, ull c) {
    ull r; asm("fma.rn.f32x2 %0, %1, %2, %3;" : "=l"(r) : "l"(a), "l"(b), "l"(c)); return r;
}
__device__ __forceinline__ float f2sum(ull v) {
    return __uint_as_float((unsigned)v) + __uint_as_float((unsigned)(v >> 32));
}

// Shared memory layout (floats):
//   Ct  [19][32][36] @ 0      (21888)  Ct[n][i][j] = cos(2*pi*n / (32*i+j+2))
//   R   [20][20][32] @ 21888  (12800)  (a,b)-pair sum of hypervol
//   Gab [32][36]     @ 34688  (1152)   P * Ct[A] * Ct[B]
//   Msc [32][36]     @ 35840  (1152)   M_w / 16 (row-padded)
//   WS2 [190][32]    @ 36992  (6080)   all 2x2x2x2 window sums (p = c*dnum+dd)
//   X   [190][32]    @ 43072  (6080)   x[p, j]
#define CT_OFF   0
#define R_OFF    21888
#define GAB_OFF  34688
#define MS_OFF   35840
#define WS_OFF   36992
#define X_OFF    43072
#define SMEM_FLOATS 49152
#define SMEM_BYTES (SMEM_FLOATS * 4)   // 196608 B, 1 CTA/SM

__global__ void __launch_bounds__(NT, 1)
pm4_kernel(const float* __restrict__ H,   // [20,20,20,20,32]
           const float* __restrict__ Mw,  // [32,32]
           const float* __restrict__ P,   // [32,32]
           float* __restrict__ out)       // [19^4, 32]
{
    extern __shared__ float s[];
    float* Ct  = s + CT_OFF;
    float* R   = s + R_OFF;
    float* Gab = s + GAB_OFF;
    float* Msc = s + MS_OFF;
    float* WS2 = s + WS_OFF;
    float* X   = s + X_OFF;

    const int tid  = threadIdx.x;
    const int lane = tid & 31;
    const int w    = tid >> 5;
    const int cp   = w >> 1;          // 0..9
    const int dg   = w & 1;           // 0..1
    const int c0   = 2 * cp;
    const int nc   = (cp == 9) ? 1 : 2;
    const int c1   = (nc == 2) ? c0 + 1 : c0;
    const int g    = gridDim.x;

    const float TWO_PI = 6.28318530717958647692f;

    // ---- once per CTA: cos table + prescaled M ----
    for (int e = tid; e < O * MM * MM; e += NT) {
        int n = e >> 10;
        int r = e & 1023;
        int i = r >> 5;
        int j = r & 31;
        float per = (float)(i * MM + j + 2);
        Ct[n * CT_STRIDE + i * ROWP + j] = cosf(TWO_PI * (float)n / per);
    }
    for (int e = tid; e < MM * MM; e += NT) {
        Msc[(e >> 5) * ROWP + (e & 31)] = Mw[e] * 0.0625f;
    }

    for (int item = blockIdx.x; item < NITEMS; item += g) {
        const int ab = item >> 1;
        const int dh = item & 1;
        const int A = ab / O;
        const int B = ab % O;
        const int dstart = dh ? 10 : 0;
        const int dnum   = dh ? 9 : 10;

        __syncthreads();   // previous item fully consumed R/X/Gab (covers init too)

        // ---- R = 2x2 (a,b) pair-sum; batched MLP-10 loads (3200 float4, 5/thread) ----
        {
            const int strideB = DM * DM * MM;        // 12800 floats
            const int strideA = DM * strideB;
            const float4* H00 = (const float4*)(H + (long)A * strideA + (long)B * strideB);
            const float4* H01 = H00 + strideB / 4;
            const float4* H10 = H00 + strideA / 4;
            const float4* H11 = H10 + strideB / 4;
            float4* R4 = (float4*)R;

            float4 pa[5], pb[5], acc[5];
            #pragma unroll
            for (int k = 0; k < 5; k++) { pa[k] = H00[tid + k * NT]; pb[k] = H01[tid + k * NT]; }
            #pragma unroll
            for (int k = 0; k < 5; k++) {
                acc[k] = make_float4(pa[k].x + pb[k].x, pa[k].y + pb[k].y,
                                     pa[k].z + pb[k].z, pa[k].w + pb[k].w);
            }
            #pragma unroll
            for (int k = 0; k < 5; k++) { pa[k] = H10[tid + k * NT]; pb[k] = H11[tid + k * NT]; }
            #pragma unroll
            for (int k = 0; k < 5; k++) {
                R4[tid + k * NT] = make_float4(acc[k].x + pa[k].x + pb[k].x,
                                               acc[k].y + pa[k].y + pb[k].y,
                                               acc[k].z + pa[k].z + pb[k].z,
                                               acc[k].w + pa[k].w + pb[k].w);
            }
        }
        // ---- Gab = P * Ct[A] * Ct[B] (cooperative) ----
        for (int e = tid; e < MM * MM; e += NT) {
            int i = e >> 5, j = e & 31;
            Gab[i * ROWP + j] = P[e] * Ct[A * CT_STRIDE + i * ROWP + j]
                                     * Ct[B * CT_STRIDE + i * ROWP + j];
        }
        __syncthreads();   // R, Gab ready

        // ---- Phase P-a: ALL 2x2 window sums -> WS2 (no syncwarp, full parallel) ----
        {
            const int nelem = O * dnum * 32;     // <= 6080
            #pragma unroll 1
            for (int e = tid; e < nelem; e += NT) {
                int l = e & 31;
                int p = e >> 5;                  // c*dnum + dd
                int c = p / dnum;
                int dd = p - c * dnum;
                int d = dstart + dd;
                const float* r0 = &R[(c * DM + d) * MM + l];
                WS2[p * 32 + l] = (r0[0] + r0[MM]) + (r0[DM * MM] + r0[DM * MM + MM]);
            }
        }
        __syncthreads();   // WS2 ready

        // ---- Phase P-b: matvec x = (M/16) * ws, warp per window, lane = j ----
        {
            ull Mreg[16];
            #pragma unroll
            for (int l4 = 0; l4 < 8; l4++) {
                ulonglong2 m = *reinterpret_cast<const ulonglong2*>(&Msc[lane * ROWP + 4 * l4]);
                Mreg[2 * l4] = m.x; Mreg[2 * l4 + 1] = m.y;
            }
            const int nwin = O * dnum;
            #pragma unroll 1
            for (int p = w; p < nwin; p += NWARP) {
                const float* wsrow = &WS2[p * 32];
                ull a0 = 0, a1 = 0;
                #pragma unroll
                for (int l4 = 0; l4 < 8; l4++) {
                    ulonglong2 wv = *reinterpret_cast<const ulonglong2*>(wsrow + 4 * l4);
                    a0 = f2fma(Mreg[2 * l4],     wv.x, a0);
                    a1 = f2fma(Mreg[2 * l4 + 1], wv.y, a1);
                }
                X[p * 32 + lane] = f2sum(a0) + f2sum(a1);
            }
        }

        // ---- per-warp G = Gab * Ct[c] (overlaps barrier skew) ----
        ull G0[16], G1[16];
        #pragma unroll
        for (int l4 = 0; l4 < 8; l4++) {
            ulonglong2 gv = *reinterpret_cast<const ulonglong2*>(&Gab[lane * ROWP + 4 * l4]);
            ulonglong2 ca = *reinterpret_cast<const ulonglong2*>(&Ct[c0 * CT_STRIDE + lane * ROWP + 4 * l4]);
            ulonglong2 cb = *reinterpret_cast<const ulonglong2*>(&Ct[c1 * CT_STRIDE + lane * ROWP + 4 * l4]);
            G0[2 * l4]     = f2mul(gv.x, ca.x);
            G0[2 * l4 + 1] = f2mul(gv.y, ca.y);
            G1[2 * l4]     = f2mul(gv.x, cb.x);
            G1[2 * l4 + 1] = f2mul(gv.y, cb.y);
        }
        __syncthreads();   // X ready

        // ---- Phase C: warp = (c-pair, d-group), lane = i (staggered dd order) ----
        {
            const int outBase = ab * (O * O) * MM;
            const int cnt = (dnum - dg + 1) >> 1;
            int it0 = cp % cnt;
            #pragma unroll 1
            for (int t = 0; t < cnt; t++) {
                int it = it0 + t; if (it >= cnt) it -= cnt;
                const int dd = dg + 2 * it;
                const int d  = dstart + dd;
                const float* cdrow = &Ct[d * CT_STRIDE + lane * ROWP];
                const float* xv0p  = &X[(c0 * dnum + dd) * 32];
                const float* xv1p  = &X[(c1 * dnum + dd) * 32];
                ull A0 = 0, A0b = 0, A1 = 0, A1b = 0;
                #pragma unroll
                for (int l4 = 0; l4 < 8; l4++) {
                    ulonglong2 cd  = *reinterpret_cast<const ulonglong2*>(cdrow + 4 * l4);
                    ulonglong2 xv0 = *reinterpret_cast<const ulonglong2*>(xv0p + 4 * l4);
                    ulonglong2 xv1 = *reinterpret_cast<const ulonglong2*>(xv1p + 4 * l4);
                    A0  = f2fma(f2mul(cd.x, G0[2 * l4]),     xv0.x, A0);
                    A0b = f2fma(f2mul(cd.y, G0[2 * l4 + 1]), xv0.y, A0b);
                    A1  = f2fma(f2mul(cd.x, G1[2 * l4]),     xv1.x, A1);
                    A1b = f2fma(f2mul(cd.y, G1[2 * l4 + 1]), xv1.y, A1b);
                }
                out[outBase + (c0 * O + d) * MM + lane] = f2sum(A0) + f2sum(A0b);
                if (nc == 2)
                    out[outBase + (c1 * O + d) * MM + lane] = f2sum(A1) + f2sum(A1b);
            }
        }
    }
}

extern "C" void kernel_launch(void* const* d_in, const int* in_sizes, int n_in,
                              void* d_out, int out_size)
{
    const float* H  = (const float*)d_in[0];
    const float* Mw = (const float*)d_in[1];
    const float* P  = (const float*)d_in[2];
    float* out = (float*)d_out;

    cudaFuncSetAttribute(pm4_kernel, cudaFuncAttributeMaxDynamicSharedMemorySize, SMEM_BYTES);

    int dev = 0, nsm = 148;
    cudaGetDevice(&dev);
    cudaDeviceGetAttribute(&nsm, cudaDevAttrMultiProcessorCount, dev);
    if (nsm <= 0) nsm = 148;
    int grid = nsm > NITEMS ? NITEMS : nsm;

    pm4_kernel<<<grid, NT, SMEM_BYTES>>>(H, Mw, P, out);
}

// round 10
// speedup vs baseline: 1.9403x; 1.1001x over previous
#include <cuda_runtime.h>
#include <cstdint>

// Problem constants (D=20, RANK=2 -> o=19 per axis, m=32)
#define O      19
#define DM     20
#define MM     32
#define ROWP   36                    // padded row (floats) -> conflict-free LDS.128
#define CT_STRIDE (MM*ROWP)          // 1152 floats per cos-table slab
#define NT     640                   // 20 warps: (c-pair 0..9) x (d-group 0..1)
#define NITEMS (O*O*2)               // (a,b) x d-half

typedef unsigned long long ull;

// ---- packed f32x2 helpers ----
__device__ __forceinline__ ull f2mul(ull a, ull b) {
    ull r; asm("mul.rn.f32x2 %0, %1, %2;" : "=l"(r) : "l"(a), "l"(b)); return r;
}
__device__ __forceinline__ ull f2fma(ull a, ull b, ull c) {
    ull r; asm("fma.rn.f32x2 %0, %1, %2, %3;" : "=l"(r) : "l"(a), "l"(b), "l"(c)); return r;
}
__device__ __forceinline__ float f2sum(ull v) {
    return __uint_as_float((unsigned)v) + __uint_as_float((unsigned)(v >> 32));
}

// Shared memory layout (floats):
//   Ct  [19][32][36] @ 0      (21888)  Ct[n][i][j] = cos(2*pi*n / (32*i+j+2))
//   R   [20][20][32] @ 21888  (12800)  (a,b)-pair sum of hypervol
//   Gab [32][36]     @ 34688  (1152)   P * Ct[A] * Ct[B]
//   Msc [32][36]     @ 35840  (1152)   M_w / 16 (row-padded)
//   X   [19][10][32] @ 36992  (6080)   x[c, d-dstart, j] for current item
//   WS  [20][32]     @ 43072  (640)    per-warp window-sum staging
#define CT_OFF   0
#define R_OFF    21888
#define GAB_OFF  34688
#define MS_OFF   35840
#define X_OFF    36992
#define WS_OFF   43072
#define SMEM_FLOATS 43712
#define SMEM_BYTES (SMEM_FLOATS * 4)

// ---- R = 2x2 (a,b) pair-sum + Gab build for item `it` ----
__device__ __forceinline__ void stage_item(const float* __restrict__ H,
                                           const float* __restrict__ P,
                                           float* __restrict__ s,
                                           int it, int tid)
{
    const int ab = it >> 1;
    const int A = ab / O;
    const int B = ab % O;
    float* R   = s + R_OFF;
    float* Gab = s + GAB_OFF;
    float* Ct  = s + CT_OFF;

    const int strideB = DM * DM * MM;        // 12800 floats
    const int strideA = DM * strideB;
    const float4* H00 = (const float4*)(H + (long)A * strideA + (long)B * strideB);
    const float4* H01 = H00 + strideB / 4;
    const float4* H10 = H00 + strideA / 4;
    const float4* H11 = H10 + strideB / 4;
    float4* R4 = (float4*)R;

    float4 pa[5], pb[5], acc[5];
    #pragma unroll
    for (int k = 0; k < 5; k++) { pa[k] = H00[tid + k * NT]; pb[k] = H01[tid + k * NT]; }
    #pragma unroll
    for (int k = 0; k < 5; k++) {
        acc[k] = make_float4(pa[k].x + pb[k].x, pa[k].y + pb[k].y,
                             pa[k].z + pb[k].z, pa[k].w + pb[k].w);
    }
    #pragma unroll
    for (int k = 0; k < 5; k++) { pa[k] = H10[tid + k * NT]; pb[k] = H11[tid + k * NT]; }
    #pragma unroll
    for (int k = 0; k < 5; k++) {
        R4[tid + k * NT] = make_float4(acc[k].x + pa[k].x + pb[k].x,
                                       acc[k].y + pa[k].y + pb[k].y,
                                       acc[k].z + pa[k].z + pb[k].z,
                                       acc[k].w + pa[k].w + pb[k].w);
    }

    // Gab = P * Ct[A] * Ct[B] (cooperative; Ct is read-only table)
    for (int e = tid; e < MM * MM; e += NT) {
        int i = e >> 5, j = e & 31;
        Gab[i * ROWP + j] = P[e] * Ct[A * CT_STRIDE + i * ROWP + j]
                                 * Ct[B * CT_STRIDE + i * ROWP + j];
    }
}

__global__ void __launch_bounds__(NT, 1)
pm4_kernel(const float* __restrict__ H,   // [20,20,20,20,32]
           const float* __restrict__ Mw,  // [32,32]
           const float* __restrict__ P,   // [32,32]
           float* __restrict__ out)       // [19^4, 32]
{
    extern __shared__ float s[];
    float* Ct  = s + CT_OFF;
    float* R   = s + R_OFF;
    float* Gab = s + GAB_OFF;
    float* Msc = s + MS_OFF;
    float* WSs = s + WS_OFF;
    float* X   = s + X_OFF;

    const int tid  = threadIdx.x;
    const int lane = tid & 31;
    const int w    = tid >> 5;
    const int cp   = w >> 1;          // 0..9
    const int dg   = w & 1;           // 0..1
    const int c0   = 2 * cp;
    const int nc   = (cp == 9) ? 1 : 2;
    const int c1   = (nc == 2) ? c0 + 1 : c0;
    const int g    = gridDim.x;

    const float TWO_PI = 6.28318530717958647692f;

    // ---- once per CTA: cos table + prescaled M ----
    for (int e = tid; e < O * MM * MM; e += NT) {
        int n = e >> 10;
        int r = e & 1023;
        int i = r >> 5;
        int j = r & 31;
        float per = (float)(i * MM + j + 2);
        Ct[n * CT_STRIDE + i * ROWP + j] = cosf(TWO_PI * (float)n / per);
    }
    for (int e = tid; e < MM * MM; e += NT) {
        Msc[(e >> 5) * ROWP + (e & 31)] = Mw[e] * 0.0625f;
    }
    __syncthreads();   // Ct ready (stage_item reads it)

    // ---- prologue: stage first item ----
    if (blockIdx.x < NITEMS)
        stage_item(H, P, s, blockIdx.x, tid);

    float* wsp = WSs + w * 32;

    for (int item = blockIdx.x; item < NITEMS; item += g) {
        const int ab = item >> 1;
        const int dh = item & 1;
        const int dstart = dh ? 10 : 0;
        const int dnum   = dh ? 9 : 10;

        __syncthreads();   // barrier2: R,Gab ready; X consumed by prev phase C

        // ---- Phase P: window-sums + matvecs -> X[c][dd][j] (lane = j) ----
        {
            ull Mreg[16];
            #pragma unroll
            for (int l4 = 0; l4 < 8; l4++) {
                ulonglong2 m = *reinterpret_cast<const ulonglong2*>(&Msc[lane * ROWP + 4 * l4]);
                Mreg[2 * l4] = m.x; Mreg[2 * l4 + 1] = m.y;
            }
            const int npairs = O * dnum;     // (c, dd) pairs
            #pragma unroll 1
            for (int p = w; p < npairs; p += 20) {
                const int c  = p / dnum;
                const int dd = p - c * dnum;
                const int d  = dstart + dd;
                float v = R[(c * DM + d) * MM + lane]
                        + R[(c * DM + d + 1) * MM + lane]
                        + R[((c + 1) * DM + d) * MM + lane]
                        + R[((c + 1) * DM + d + 1) * MM + lane];
                wsp[lane] = v;
                __syncwarp();
                ull a0 = 0, a1 = 0;
                #pragma unroll
                for (int l4 = 0; l4 < 8; l4++) {
                    ulonglong2 wv = *reinterpret_cast<const ulonglong2*>(&wsp[4 * l4]);
                    a0 = f2fma(Mreg[2 * l4],     wv.x, a0);
                    a1 = f2fma(Mreg[2 * l4 + 1], wv.y, a1);
                }
                X[(c * 10 + dd) * 32 + lane] = f2sum(a0) + f2sum(a1);
                __syncwarp();
            }
        }

        // ---- per-warp G = Gab * Ct[c] (reads Gab; before barrier3) ----
        ull G0[16], G1[16];
        #pragma unroll
        for (int l4 = 0; l4 < 8; l4++) {
            ulonglong2 gv = *reinterpret_cast<const ulonglong2*>(&Gab[lane * ROWP + 4 * l4]);
            ulonglong2 ca = *reinterpret_cast<const ulonglong2*>(&Ct[c0 * CT_STRIDE + lane * ROWP + 4 * l4]);
            ulonglong2 cb = *reinterpret_cast<const ulonglong2*>(&Ct[c1 * CT_STRIDE + lane * ROWP + 4 * l4]);
            G0[2 * l4]     = f2mul(gv.x, ca.x);
            G0[2 * l4 + 1] = f2mul(gv.y, ca.y);
            G1[2 * l4]     = f2mul(gv.x, cb.x);
            G1[2 * l4 + 1] = f2mul(gv.y, cb.y);
        }
        __syncthreads();   // barrier3: X ready; R,Gab consumed

        // ---- Phase C: warp = (c-pair, d-group), lane = i (staggered dd) ----
        {
            const int outBase = ab * (O * O) * MM;
            const int cnt = (dnum - dg + 1) >> 1;
            int it0 = cp % cnt;
            #pragma unroll 1
            for (int t = 0; t < cnt; t++) {
                int it = it0 + t; if (it >= cnt) it -= cnt;
                const int dd = dg + 2 * it;
                const int d  = dstart + dd;
                const float* cdrow = &Ct[d * CT_STRIDE + lane * ROWP];
                const float* xv0p  = &X[(c0 * 10 + dd) * 32];
                const float* xv1p  = &X[(c1 * 10 + dd) * 32];
                ull A0 = 0, A0b = 0, A1 = 0, A1b = 0;
                #pragma unroll
                for (int l4 = 0; l4 < 8; l4++) {
                    ulonglong2 cd  = *reinterpret_cast<const ulonglong2*>(cdrow + 4 * l4);
                    ulonglong2 xv0 = *reinterpret_cast<const ulonglong2*>(xv0p + 4 * l4);
                    ulonglong2 xv1 = *reinterpret_cast<const ulonglong2*>(xv1p + 4 * l4);
                    A0  = f2fma(f2mul(cd.x, G0[2 * l4]),     xv0.x, A0);
                    A0b = f2fma(f2mul(cd.y, G0[2 * l4 + 1]), xv0.y, A0b);
                    A1  = f2fma(f2mul(cd.x, G1[2 * l4]),     xv1.x, A1);
                    A1b = f2fma(f2mul(cd.y, G1[2 * l4 + 1]), xv1.y, A1b);
                }
                out[outBase + (c0 * O + d) * MM + lane] = f2sum(A0) + f2sum(A0b);
                if (nc == 2)
                    out[outBase + (c1 * O + d) * MM + lane] = f2sum(A1) + f2sum(A1b);
            }
        }

        // ---- tail: stage next item (R + Gab) — overlaps other warps' phase C ----
        if (item + g < NITEMS)
            stage_item(H, P, s, item + g, tid);
    }
}

extern "C" void kernel_launch(void* const* d_in, const int* in_sizes, int n_in,
                              void* d_out, int out_size)
{
    const float* H  = (const float*)d_in[0];
    const float* Mw = (const float*)d_in[1];
    const float* P  = (const float*)d_in[2];
    float* out = (float*)d_out;

    cudaFuncSetAttribute(pm4_kernel, cudaFuncAttributeMaxDynamicSharedMemorySize, SMEM_BYTES);

    int dev = 0, nsm = 148;
    cudaGetDevice(&dev);
    cudaDeviceGetAttribute(&nsm, cudaDevAttrMultiProcessorCount, dev);
    if (nsm <= 0) nsm = 148;
    int grid = nsm > NITEMS ? NITEMS : nsm;

    pm4_kernel<<<grid, NT, SMEM_BYTES>>>(H, Mw, P, out);
}